// round 15
// baseline (speedup 1.0000x reference)
#include <cuda_runtime.h>
#include <cstdint>

// Problem dims
#define BB       4096
#define DIN      784
#define DZ       128
#define NTRIALS  256
#define BZ       (BB * DZ)
#define KSPLIT   7          // 49 K-tiles of 16 = 7 chunks x 7 tiles, exact

// SMEM k-row strides (floats), padded so stride % 32 == 8.
#define SA 136
#define SB 72

// Scratch (device globals => no allocations).
__device__ float g_part[KSPLIT][BZ];   // split-K partials for encoder

__device__ __forceinline__ float tanhf_fast(float x) {
    float y;
    asm("tanh.approx.f32 %0, %1;" : "=f"(y) : "f"(x));
    return y;
}

__device__ __forceinline__ uint32_t f2tf32(float x) {
    uint32_t r;
    asm("cvt.rna.tf32.f32 %0, %1;" : "=r"(r) : "f"(x));
    return r;
}

__device__ __forceinline__ void mma_tf32(float* c,
                                         uint32_t a0, uint32_t a1,
                                         uint32_t a2, uint32_t a3,
                                         uint32_t b0, uint32_t b1)
{
    asm volatile(
        "mma.sync.aligned.m16n8k8.row.col.f32.tf32.tf32.f32 "
        "{%0,%1,%2,%3}, {%4,%5,%6,%7}, {%8,%9}, {%0,%1,%2,%3};"
        : "+f"(c[0]), "+f"(c[1]), "+f"(c[2]), "+f"(c[3])
        : "r"(a0), "r"(a1), "r"(a2), "r"(a3), "r"(b0), "r"(b1));
}

__device__ __forceinline__ int permp(int r) { return (r & 7) * 4 + (r >> 3); }

// Warp-tile MMA consumer: 8 warps = 4(m) x 2(n); warp computes 32x32.
__device__ __forceinline__ void warp_mma_tile(const float* Asp, const float* Bsp,
                                              int wm, int wn, int lane,
                                              float acc[2][4][4])
{
    const int g  = lane >> 2;
    const int tg = lane & 3;
    #pragma unroll
    for (int kk = 0; kk < 16; kk += 8) {
        const int ka = kk + tg;
        uint4 a_lo = *(const uint4*)&Asp[ka * SA + wm * 32 + g * 4];
        uint4 a_hi = *(const uint4*)&Asp[(ka + 4) * SA + wm * 32 + g * 4];
        uint4 b_lo = *(const uint4*)&Bsp[ka * SB + wn * 32 + g * 4];
        uint4 b_hi = *(const uint4*)&Bsp[(ka + 4) * SB + wn * 32 + g * 4];

        uint32_t bl[4] = {b_lo.x, b_lo.y, b_lo.z, b_lo.w};
        uint32_t bh[4] = {b_hi.x, b_hi.y, b_hi.z, b_hi.w};

        #pragma unroll
        for (int nt = 0; nt < 4; nt++) {
            mma_tf32(acc[0][nt], a_lo.x, a_lo.y, a_hi.x, a_hi.y, bl[nt], bh[nt]);
            mma_tf32(acc[1][nt], a_lo.z, a_lo.w, a_hi.z, a_hi.w, bl[nt], bh[nt]);
        }
    }
}

// ---------------------------------------------------------------------------
// Encoder split-K GEMM — tf32 MMA + prefetch + DOUBLE-BUFFERED SMEM:
// one __syncthreads per K-tile (was two). Iteration t: MMA reads buf[t&1]
// while prefetched registers for tile t+1 are stored into buf[1-(t&1)];
// the end-of-iteration sync orders those writes before the next MMA.
// BM=128, BN=64, BK=16. grid = (2, 32, 7).
// ---------------------------------------------------------------------------
__global__ __launch_bounds__(256)
void enc_gemm_splitk(const float* __restrict__ A,
                     const float* __restrict__ Bm)
{
    __shared__ float Asp[2][16 * SA];
    __shared__ float Bsp[2][16 * SB];

    const int tid = threadIdx.x;
    const int m0  = blockIdx.y * 128;
    const int n0  = blockIdx.x * 64;
    const int chunk = blockIdx.z;

    const int wid  = tid >> 5, lane = tid & 31;
    const int wm   = wid >> 1, wn   = wid & 1;

    const int a_m = tid >> 1;
    const int a_k = (tid & 1) * 8;
    const int pa  = (a_m >> 5) * 32 + permp(a_m & 31);
    const int b_k = tid >> 4;
    const int b_n = (tid & 15) * 4;

    float acc[2][4][4];
    #pragma unroll
    for (int i = 0; i < 2; i++)
        #pragma unroll
        for (int j = 0; j < 4; j++)
            #pragma unroll
            for (int q = 0; q < 4; q++) acc[i][j][q] = 0.f;

    const int tbase = chunk * 7;
    float4 av0, av1, bv;

    // preload tile 0 -> buffer 0
    {
        const int k0 = tbase * 16;
        av0 = *(const float4*)&A[(size_t)(m0 + a_m) * DIN + k0 + a_k];
        av1 = *(const float4*)&A[(size_t)(m0 + a_m) * DIN + k0 + a_k + 4];
        bv  = *(const float4*)&Bm[(size_t)(k0 + b_k) * DZ + n0 + b_n];

        float af[8] = {av0.x, av0.y, av0.z, av0.w, av1.x, av1.y, av1.z, av1.w};
        #pragma unroll
        for (int j = 0; j < 8; j++)
            Asp[0][(a_k + j) * SA + pa] = __uint_as_float(f2tf32(af[j]));
        float bf[4] = {bv.x, bv.y, bv.z, bv.w};
        #pragma unroll
        for (int j = 0; j < 4; j++) {
            const int c = b_n + j;
            Bsp[0][b_k * SB + (c >> 5) * 32 + permp(c & 31)] =
                __uint_as_float(f2tf32(bf[j]));
        }
    }
    __syncthreads();

    #pragma unroll 1
    for (int t = 0; t < 7; t++) {
        const int cur = t & 1;

        if (t < 6) {    // prefetch next tile: overlaps with MMA below
            const int k0 = (tbase + t + 1) * 16;
            av0 = *(const float4*)&A[(size_t)(m0 + a_m) * DIN + k0 + a_k];
            av1 = *(const float4*)&A[(size_t)(m0 + a_m) * DIN + k0 + a_k + 4];
            bv  = *(const float4*)&Bm[(size_t)(k0 + b_k) * DZ + n0 + b_n];
        }

        warp_mma_tile(Asp[cur], Bsp[cur], wm, wn, lane, acc);

        if (t < 6) {    // store into the OTHER buffer, single sync
            const int nxt = 1 - cur;
            float af[8] = {av0.x, av0.y, av0.z, av0.w,
                           av1.x, av1.y, av1.z, av1.w};
            #pragma unroll
            for (int j = 0; j < 8; j++)
                Asp[nxt][(a_k + j) * SA + pa] = __uint_as_float(f2tf32(af[j]));
            float bf[4] = {bv.x, bv.y, bv.z, bv.w};
            #pragma unroll
            for (int j = 0; j < 4; j++) {
                const int c = b_n + j;
                Bsp[nxt][b_k * SB + (c >> 5) * 32 + permp(c & 31)] =
                    __uint_as_float(f2tf32(bf[j]));
            }
            __syncthreads();
        }
    }

    float* dst = g_part[chunk];
    const int g  = lane >> 2;
    const int tg = lane & 3;
    #pragma unroll
    for (int nt = 0; nt < 4; nt++) {
        const int n_el = n0 + wn * 32 + nt * 8 + tg * 2;
        #pragma unroll
        for (int mt = 0; mt < 2; mt++) {
            const int m_el = m0 + wm * 32 + mt * 16 + g;
            *(float2*)&dst[(size_t)m_el * DZ + n_el] =
                make_float2(acc[mt][nt][0], acc[mt][nt][1]);
            *(float2*)&dst[(size_t)(m_el + 8) * DZ + n_el] =
                make_float2(acc[mt][nt][2], acc[mt][nt][3]);
        }
    }
}

// ---------------------------------------------------------------------------
// Fused encoder-epilogue + exponential race — EXACT R13 version (best
// measured race, 77.9us total pass). Contiguous coalesced loads, prefetch
// at loop top with no compute dependency, plain LG2 chain.
// Exit: s * min(128, 2*rate) <= 5e-4 * zacc (expected tail ~2.5e-4 rel).
// ---------------------------------------------------------------------------
__global__ __launch_bounds__(256)
void race_kernel(const float* __restrict__ u,
                 const float* __restrict__ bias,
                 const float* __restrict__ prior,
                 float* __restrict__ out_du,
                 float* __restrict__ zout)
{
    const int i = blockIdx.x * blockDim.x + threadIdx.x;
    const int n = i & (DZ - 1);

    float v = g_part[0][i] + g_part[1][i] + g_part[2][i] + g_part[3][i]
            + g_part[4][i] + g_part[5][i] + g_part[6][i] + bias[n];
    float du = fminf(v, 5.0f);
    out_du[i] = du;
    float lr = fminf(du + fminf(prior[n], 5.0f), 5.0f);
    float rate = __expf(lr) + 1e-6f;
    const float a = 0.34657359f / rate;                // 0.5*ln2/rate
    const float exit_f = fminf(128.0f, 2.0f * rate);   // tail factor

    const float* up = u + i;

    float cum = 0.f, zacc = 0.f;
    float buf[8];
    #pragma unroll
    for (int j = 0; j < 8; j++) buf[j] = up[(size_t)j * BZ];

    #pragma unroll 1
    for (int t0 = 0; t0 < NTRIALS; t0 += 8) {
        float nbuf[8];
        if (t0 + 8 < NTRIALS) {
            #pragma unroll
            for (int j = 0; j < 8; j++)
                nbuf[j] = up[(size_t)(t0 + 8 + j) * BZ];
        }

        float s = 0.f;
        #pragma unroll
        for (int j = 0; j < 8; j++) {
            cum += __log2f(1.0f - buf[j]);          // negative, decreasing
            float h  = fmaf(cum, a, 0.5f);          // (1-times)/2
            s = fmaf(0.5f, tanhf_fast(h), 0.5f);    // sigmoid(1-times)
            zacc += s;
        }

        if (__all_sync(0xFFFFFFFFu, s * exit_f <= zacc * 5e-4f + 1e-30f))
            break;

        #pragma unroll
        for (int j = 0; j < 8; j++) buf[j] = nbuf[j];
    }
    zout[i] = zacc;
}

// ---------------------------------------------------------------------------
// Decoder GEMM — exact R8 version (measured ~8.5us; prefetch variant
// regressed it via register pressure on guarded loads — do not touch).
// y = sigmoid(z @ W_dec + b_dec). BM=128, BN=64, BK=16, K=128. grid=(13,32).
// ---------------------------------------------------------------------------
__global__ __launch_bounds__(256)
void dec_gemm(const float* __restrict__ A,
              const float* __restrict__ Bm,
              const float* __restrict__ bias,
              float* __restrict__ out)
{
    const int N = DIN;
    __shared__ float Asp[16 * SA];
    __shared__ float Bsp[16 * SB];

    const int tid = threadIdx.x;
    const int m0  = blockIdx.y * 128;
    const int n0  = blockIdx.x * 64;

    const int wid  = tid >> 5, lane = tid & 31;
    const int wm   = wid >> 1, wn   = wid & 1;

    const int a_m = tid >> 1;
    const int a_k = (tid & 1) * 8;
    const int pa  = (a_m >> 5) * 32 + permp(a_m & 31);
    const int b_k = tid >> 4;
    const int b_n = (tid & 15) * 4;
    const int gn  = n0 + b_n;

    float acc[2][4][4];
    #pragma unroll
    for (int i = 0; i < 2; i++)
        #pragma unroll
        for (int j = 0; j < 4; j++)
            #pragma unroll
            for (int q = 0; q < 4; q++) acc[i][j][q] = 0.f;

    #pragma unroll 1
    for (int t = 0; t < 8; t++) {
        const int k0 = t * 16;

        float4 av0 = *(const float4*)&A[(size_t)(m0 + a_m) * DZ + k0 + a_k];
        float4 av1 = *(const float4*)&A[(size_t)(m0 + a_m) * DZ + k0 + a_k + 4];
        float4 bv  = make_float4(0.f, 0.f, 0.f, 0.f);
        if (gn + 3 < N)
            bv = *(const float4*)&Bm[(size_t)(k0 + b_k) * N + gn];

        float af[8] = {av0.x, av0.y, av0.z, av0.w, av1.x, av1.y, av1.z, av1.w};
        #pragma unroll
        for (int j = 0; j < 8; j++)
            Asp[(a_k + j) * SA + pa] = __uint_as_float(f2tf32(af[j]));

        float bf[4] = {bv.x, bv.y, bv.z, bv.w};
        #pragma unroll
        for (int j = 0; j < 4; j++) {
            const int c = b_n + j;
            Bsp[b_k * SB + (c >> 5) * 32 + permp(c & 31)] =
                __uint_as_float(f2tf32(bf[j]));
        }
        __syncthreads();

        warp_mma_tile(Asp, Bsp, wm, wn, lane, acc);
        __syncthreads();
    }

    const int g  = lane >> 2;
    const int tg = lane & 3;
    #pragma unroll
    for (int nt = 0; nt < 4; nt++) {
        const int n_el = n0 + wn * 32 + nt * 8 + tg * 2;
        if (n_el >= N) continue;
        const float bi0 = bias[n_el], bi1 = bias[n_el + 1];
        #pragma unroll
        for (int mt = 0; mt < 2; mt++) {
            const int m_el = m0 + wm * 32 + mt * 16 + g;
            float v0 = acc[mt][nt][0] + bi0;
            float v1 = acc[mt][nt][1] + bi1;
            float v2 = acc[mt][nt][2] + bi0;
            float v3 = acc[mt][nt][3] + bi1;
            v0 = __fdividef(1.0f, 1.0f + __expf(-v0));
            v1 = __fdividef(1.0f, 1.0f + __expf(-v1));
            v2 = __fdividef(1.0f, 1.0f + __expf(-v2));
            v3 = __fdividef(1.0f, 1.0f + __expf(-v3));
            *(float2*)&out[(size_t)m_el * N + n_el]       = make_float2(v0, v1);
            *(float2*)&out[(size_t)(m_el + 8) * N + n_el] = make_float2(v2, v3);
        }
    }
}

// ---------------------------------------------------------------------------
// Launch. Input order: x, u, W_enc, b_enc, W_dec, b_dec, prior
// Output: du [BZ] | z [BZ] | y [B*DIN]
// ---------------------------------------------------------------------------
extern "C" void kernel_launch(void* const* d_in, const int* in_sizes, int n_in,
                              void* d_out, int out_size)
{
    const float* x     = (const float*)d_in[0];
    const float* u     = (const float*)d_in[1];
    const float* W_enc = (const float*)d_in[2];
    const float* b_enc = (const float*)d_in[3];
    const float* W_dec = (const float*)d_in[4];
    const float* b_dec = (const float*)d_in[5];
    const float* prior = (const float*)d_in[6];

    float* out_du = (float*)d_out;
    float* out_z  = out_du + (size_t)BZ;
    float* out_y  = out_z  + (size_t)BZ;

    // 1) encoder split-K GEMM (tf32 MMA, double-buffered)
    {
        dim3 grid(DZ / 64, BB / 128, KSPLIT);
        enc_gemm_splitk<<<grid, 256>>>(x, W_enc);
    }
    // 2) fused epilogue + exponential race -> du, z
    race_kernel<<<BZ / 256, 256>>>(u, b_enc, prior, out_du, out_z);

    // 3) decoder GEMM (tf32 MMA): y = sigmoid(z @ W_dec + b_dec)
    {
        dim3 grid((DIN + 63) / 64, BB / 128);
        dec_gemm<<<grid, 256>>>(out_z, W_dec, b_dec, out_y);
    }
}

// round 16
// speedup vs baseline: 1.0445x; 1.0445x over previous
#include <cuda_runtime.h>
#include <cstdint>

// Problem dims
#define BB       4096
#define DIN      784
#define DZ       128
#define NTRIALS  256
#define BZ       (BB * DZ)
#define KSPLIT   7          // 49 K-tiles of 16 = 7 chunks x 7 tiles, exact

// SMEM k-row strides (floats), padded so stride % 32 == 8.
#define SA 136
#define SB 72

// Scratch (device globals => no allocations).
__device__ float g_part[KSPLIT][BZ];   // split-K partials for encoder

__device__ __forceinline__ float tanhf_fast(float x) {
    float y;
    asm("tanh.approx.f32 %0, %1;" : "=f"(y) : "f"(x));
    return y;
}

__device__ __forceinline__ uint32_t f2tf32(float x) {
    uint32_t r;
    asm("cvt.rna.tf32.f32 %0, %1;" : "=r"(r) : "f"(x));
    return r;
}

__device__ __forceinline__ void mma_tf32(float* c,
                                         uint32_t a0, uint32_t a1,
                                         uint32_t a2, uint32_t a3,
                                         uint32_t b0, uint32_t b1)
{
    asm volatile(
        "mma.sync.aligned.m16n8k8.row.col.f32.tf32.tf32.f32 "
        "{%0,%1,%2,%3}, {%4,%5,%6,%7}, {%8,%9}, {%0,%1,%2,%3};"
        : "+f"(c[0]), "+f"(c[1]), "+f"(c[2]), "+f"(c[3])
        : "r"(a0), "r"(a1), "r"(a2), "r"(a3), "r"(b0), "r"(b1));
}

__device__ __forceinline__ int permp(int r) { return (r & 7) * 4 + (r >> 3); }

// Warp-tile MMA consumer: 8 warps = 4(m) x 2(n); warp computes 32x32.
__device__ __forceinline__ void warp_mma_tile(const float* Asp, const float* Bsp,
                                              int wm, int wn, int lane,
                                              float acc[2][4][4])
{
    const int g  = lane >> 2;
    const int tg = lane & 3;
    #pragma unroll
    for (int kk = 0; kk < 16; kk += 8) {
        const int ka = kk + tg;
        uint4 a_lo = *(const uint4*)&Asp[ka * SA + wm * 32 + g * 4];
        uint4 a_hi = *(const uint4*)&Asp[(ka + 4) * SA + wm * 32 + g * 4];
        uint4 b_lo = *(const uint4*)&Bsp[ka * SB + wn * 32 + g * 4];
        uint4 b_hi = *(const uint4*)&Bsp[(ka + 4) * SB + wn * 32 + g * 4];

        uint32_t bl[4] = {b_lo.x, b_lo.y, b_lo.z, b_lo.w};
        uint32_t bh[4] = {b_hi.x, b_hi.y, b_hi.z, b_hi.w};

        #pragma unroll
        for (int nt = 0; nt < 4; nt++) {
            mma_tf32(acc[0][nt], a_lo.x, a_lo.y, a_hi.x, a_hi.y, bl[nt], bh[nt]);
            mma_tf32(acc[1][nt], a_lo.z, a_lo.w, a_hi.z, a_hi.w, bl[nt], bh[nt]);
        }
    }
}

// ---------------------------------------------------------------------------
// Encoder split-K GEMM — exact R13 single-buffer structure (16.7us measured;
// R14 double-buffer regressed to 18.0). ONLY change: __launch_bounds__(256,3)
// to cap regs <= ~85 and lift occupancy from 2 to 3 CTAs/SM (kernel is
// latency-bound: issue 31.5%, occ 19.7%).
// BM=128, BN=64, BK=16. grid = (2, 32, 7).
// ---------------------------------------------------------------------------
__global__ __launch_bounds__(256, 3)
void enc_gemm_splitk(const float* __restrict__ A,
                     const float* __restrict__ Bm)
{
    __shared__ float Asp[16 * SA];
    __shared__ float Bsp[16 * SB];

    const int tid = threadIdx.x;
    const int m0  = blockIdx.y * 128;
    const int n0  = blockIdx.x * 64;
    const int chunk = blockIdx.z;

    const int wid  = tid >> 5, lane = tid & 31;
    const int wm   = wid >> 1, wn   = wid & 1;

    const int a_m = tid >> 1;
    const int a_k = (tid & 1) * 8;
    const int pa  = (a_m >> 5) * 32 + permp(a_m & 31);
    const int b_k = tid >> 4;
    const int b_n = (tid & 15) * 4;

    float acc[2][4][4];
    #pragma unroll
    for (int i = 0; i < 2; i++)
        #pragma unroll
        for (int j = 0; j < 4; j++)
            #pragma unroll
            for (int q = 0; q < 4; q++) acc[i][j][q] = 0.f;

    const int tbase = chunk * 7;
    float4 av0, av1, bv;
    {
        const int k0 = tbase * 16;
        av0 = *(const float4*)&A[(size_t)(m0 + a_m) * DIN + k0 + a_k];
        av1 = *(const float4*)&A[(size_t)(m0 + a_m) * DIN + k0 + a_k + 4];
        bv  = *(const float4*)&Bm[(size_t)(k0 + b_k) * DZ + n0 + b_n];
    }

    #pragma unroll 1
    for (int t = 0; t < 7; t++) {
        float af[8] = {av0.x, av0.y, av0.z, av0.w, av1.x, av1.y, av1.z, av1.w};
        #pragma unroll
        for (int j = 0; j < 8; j++)
            Asp[(a_k + j) * SA + pa] = __uint_as_float(f2tf32(af[j]));
        float bf[4] = {bv.x, bv.y, bv.z, bv.w};
        #pragma unroll
        for (int j = 0; j < 4; j++) {
            const int c = b_n + j;
            Bsp[b_k * SB + (c >> 5) * 32 + permp(c & 31)] =
                __uint_as_float(f2tf32(bf[j]));
        }
        __syncthreads();

        if (t < 6) {    // prefetch next tile: overlaps with MMA below
            const int k0 = (tbase + t + 1) * 16;
            av0 = *(const float4*)&A[(size_t)(m0 + a_m) * DIN + k0 + a_k];
            av1 = *(const float4*)&A[(size_t)(m0 + a_m) * DIN + k0 + a_k + 4];
            bv  = *(const float4*)&Bm[(size_t)(k0 + b_k) * DZ + n0 + b_n];
        }

        warp_mma_tile(Asp, Bsp, wm, wn, lane, acc);
        __syncthreads();
    }

    float* dst = g_part[chunk];
    const int g  = lane >> 2;
    const int tg = lane & 3;
    #pragma unroll
    for (int nt = 0; nt < 4; nt++) {
        const int n_el = n0 + wn * 32 + nt * 8 + tg * 2;
        #pragma unroll
        for (int mt = 0; mt < 2; mt++) {
            const int m_el = m0 + wm * 32 + mt * 16 + g;
            *(float2*)&dst[(size_t)m_el * DZ + n_el] =
                make_float2(acc[mt][nt][0], acc[mt][nt][1]);
            *(float2*)&dst[(size_t)(m_el + 8) * DZ + n_el] =
                make_float2(acc[mt][nt][2], acc[mt][nt][3]);
        }
    }
}

// ---------------------------------------------------------------------------
// Fused encoder-epilogue + exponential race — R13 structure (best measured).
// Contiguous coalesced loads (warp = one 128B line/trial), prefetch at loop
// top with no compute dependency, plain LG2 chain. ONLY change vs R13:
// exit threshold 5e-4 -> 8e-4 (expected skipped tail ~4e-4, 2.5x under the
// per-output 1e-3 budget; binding output error is the tf32 du at 2.93e-4).
// ---------------------------------------------------------------------------
__global__ __launch_bounds__(256)
void race_kernel(const float* __restrict__ u,
                 const float* __restrict__ bias,
                 const float* __restrict__ prior,
                 float* __restrict__ out_du,
                 float* __restrict__ zout)
{
    const int i = blockIdx.x * blockDim.x + threadIdx.x;
    const int n = i & (DZ - 1);

    float v = g_part[0][i] + g_part[1][i] + g_part[2][i] + g_part[3][i]
            + g_part[4][i] + g_part[5][i] + g_part[6][i] + bias[n];
    float du = fminf(v, 5.0f);
    out_du[i] = du;
    float lr = fminf(du + fminf(prior[n], 5.0f), 5.0f);
    float rate = __expf(lr) + 1e-6f;
    const float a = 0.34657359f / rate;                // 0.5*ln2/rate
    const float exit_f = fminf(128.0f, 2.0f * rate);   // tail factor

    const float* up = u + i;

    float cum = 0.f, zacc = 0.f;
    float buf[8];
    #pragma unroll
    for (int j = 0; j < 8; j++) buf[j] = up[(size_t)j * BZ];

    #pragma unroll 1
    for (int t0 = 0; t0 < NTRIALS; t0 += 8) {
        float nbuf[8];
        if (t0 + 8 < NTRIALS) {
            #pragma unroll
            for (int j = 0; j < 8; j++)
                nbuf[j] = up[(size_t)(t0 + 8 + j) * BZ];
        }

        float s = 0.f;
        #pragma unroll
        for (int j = 0; j < 8; j++) {
            cum += __log2f(1.0f - buf[j]);          // negative, decreasing
            float h  = fmaf(cum, a, 0.5f);          // (1-times)/2
            s = fmaf(0.5f, tanhf_fast(h), 0.5f);    // sigmoid(1-times)
            zacc += s;
        }

        if (__all_sync(0xFFFFFFFFu, s * exit_f <= zacc * 8e-4f + 1e-30f))
            break;

        #pragma unroll
        for (int j = 0; j < 8; j++) buf[j] = nbuf[j];
    }
    zout[i] = zacc;
}

// ---------------------------------------------------------------------------
// Decoder GEMM — exact R8 version (measured ~8.5us; do not touch).
// y = sigmoid(z @ W_dec + b_dec). BM=128, BN=64, BK=16, K=128. grid=(13,32).
// ---------------------------------------------------------------------------
__global__ __launch_bounds__(256)
void dec_gemm(const float* __restrict__ A,
              const float* __restrict__ Bm,
              const float* __restrict__ bias,
              float* __restrict__ out)
{
    const int N = DIN;
    __shared__ float Asp[16 * SA];
    __shared__ float Bsp[16 * SB];

    const int tid = threadIdx.x;
    const int m0  = blockIdx.y * 128;
    const int n0  = blockIdx.x * 64;

    const int wid  = tid >> 5, lane = tid & 31;
    const int wm   = wid >> 1, wn   = wid & 1;

    const int a_m = tid >> 1;
    const int a_k = (tid & 1) * 8;
    const int pa  = (a_m >> 5) * 32 + permp(a_m & 31);
    const int b_k = tid >> 4;
    const int b_n = (tid & 15) * 4;
    const int gn  = n0 + b_n;

    float acc[2][4][4];
    #pragma unroll
    for (int i = 0; i < 2; i++)
        #pragma unroll
        for (int j = 0; j < 4; j++)
            #pragma unroll
            for (int q = 0; q < 4; q++) acc[i][j][q] = 0.f;

    #pragma unroll 1
    for (int t = 0; t < 8; t++) {
        const int k0 = t * 16;

        float4 av0 = *(const float4*)&A[(size_t)(m0 + a_m) * DZ + k0 + a_k];
        float4 av1 = *(const float4*)&A[(size_t)(m0 + a_m) * DZ + k0 + a_k + 4];
        float4 bv  = make_float4(0.f, 0.f, 0.f, 0.f);
        if (gn + 3 < N)
            bv = *(const float4*)&Bm[(size_t)(k0 + b_k) * N + gn];

        float af[8] = {av0.x, av0.y, av0.z, av0.w, av1.x, av1.y, av1.z, av1.w};
        #pragma unroll
        for (int j = 0; j < 8; j++)
            Asp[(a_k + j) * SA + pa] = __uint_as_float(f2tf32(af[j]));

        float bf[4] = {bv.x, bv.y, bv.z, bv.w};
        #pragma unroll
        for (int j = 0; j < 4; j++) {
            const int c = b_n + j;
            Bsp[b_k * SB + (c >> 5) * 32 + permp(c & 31)] =
                __uint_as_float(f2tf32(bf[j]));
        }
        __syncthreads();

        warp_mma_tile(Asp, Bsp, wm, wn, lane, acc);
        __syncthreads();
    }

    const int g  = lane >> 2;
    const int tg = lane & 3;
    #pragma unroll
    for (int nt = 0; nt < 4; nt++) {
        const int n_el = n0 + wn * 32 + nt * 8 + tg * 2;
        if (n_el >= N) continue;
        const float bi0 = bias[n_el], bi1 = bias[n_el + 1];
        #pragma unroll
        for (int mt = 0; mt < 2; mt++) {
            const int m_el = m0 + wm * 32 + mt * 16 + g;
            float v0 = acc[mt][nt][0] + bi0;
            float v1 = acc[mt][nt][1] + bi1;
            float v2 = acc[mt][nt][2] + bi0;
            float v3 = acc[mt][nt][3] + bi1;
            v0 = __fdividef(1.0f, 1.0f + __expf(-v0));
            v1 = __fdividef(1.0f, 1.0f + __expf(-v1));
            v2 = __fdividef(1.0f, 1.0f + __expf(-v2));
            v3 = __fdividef(1.0f, 1.0f + __expf(-v3));
            *(float2*)&out[(size_t)m_el * N + n_el]       = make_float2(v0, v1);
            *(float2*)&out[(size_t)(m_el + 8) * N + n_el] = make_float2(v2, v3);
        }
    }
}

// ---------------------------------------------------------------------------
// Launch. Input order: x, u, W_enc, b_enc, W_dec, b_dec, prior
// Output: du [BZ] | z [BZ] | y [B*DIN]
// ---------------------------------------------------------------------------
extern "C" void kernel_launch(void* const* d_in, const int* in_sizes, int n_in,
                              void* d_out, int out_size)
{
    const float* x     = (const float*)d_in[0];
    const float* u     = (const float*)d_in[1];
    const float* W_enc = (const float*)d_in[2];
    const float* b_enc = (const float*)d_in[3];
    const float* W_dec = (const float*)d_in[4];
    const float* b_dec = (const float*)d_in[5];
    const float* prior = (const float*)d_in[6];

    float* out_du = (float*)d_out;
    float* out_z  = out_du + (size_t)BZ;
    float* out_y  = out_z  + (size_t)BZ;

    // 1) encoder split-K GEMM (tf32 MMA)
    {
        dim3 grid(DZ / 64, BB / 128, KSPLIT);
        enc_gemm_splitk<<<grid, 256>>>(x, W_enc);
    }
    // 2) fused epilogue + exponential race -> du, z
    race_kernel<<<BZ / 256, 256>>>(u, b_enc, prior, out_du, out_z);

    // 3) decoder GEMM (tf32 MMA): y = sigmoid(z @ W_dec + b_dec)
    {
        dim3 grid((DIN + 63) / 64, BB / 128);
        dec_gemm<<<grid, 256>>>(out_z, W_dec, b_dec, out_y);
    }
}